// round 1
// baseline (speedup 1.0000x reference)
#include <cuda_runtime.h>
#include <math.h>

// Problem constants
#define KNOTS   16
#define BOUNDV  5.0f
#define XDIM    6
#define CDIM    4
#define HID     128
#define SPLD    47      // 3*KNOTS-1
#define LOWERD  3
#define OUTD    141     // LOWERD*SPLD
#define OUTP    144     // padded

#define ROWS    64      // rows per block
#define NTHREADS 256

// Shared memory layout (floats)
//  sW2   : 16384  (128x128)
//  sW3   : 18432  (128x144 padded)
//  sW1   :  1024  (8x128, rows 0..6 valid)
//  sB1   :   128
//  sB2   :   128
//  sB3   :   144  (padded)
//  sH    :   512  (64x8: cols 0..2 upper, 3..6 c)
//  sLow  :   256  (64x4)
//  sLd   :   256  (64x4)
//  U     :  9216  (union: T1T[128][64] then P[64][144])
//  T2    :  8192  (T2T[128][64])
#define OFF_W2  0
#define OFF_W3  16384
#define OFF_W1  (16384+18432)
#define OFF_B1  (OFF_W1+1024)
#define OFF_B2  (OFF_B1+128)
#define OFF_B3  (OFF_B2+128)
#define OFF_H   (OFF_B3+144)
#define OFF_LOW (OFF_H+512)
#define OFF_LD  (OFF_LOW+256)
#define OFF_U   (OFF_LD+256)
#define OFF_T2  (OFF_U+9216)
#define SMEM_FLOATS (OFF_T2+8192)
#define SMEM_BYTES (SMEM_FLOATS*4)

__device__ __forceinline__ float softplus_f(float v) {
    // max(v,0) + log1p(exp(-|v|))  (matches jax.nn.softplus)
    return fmaxf(v, 0.0f) + log1pf(__expf(-fabsf(v)));
}

__global__ __launch_bounds__(NTHREADS, 1)
void nsc_kernel(const float* __restrict__ x, const float* __restrict__ c,
                const float* __restrict__ W1, const float* __restrict__ b1,
                const float* __restrict__ W2, const float* __restrict__ b2,
                const float* __restrict__ W3, const float* __restrict__ b3,
                float* __restrict__ out, int B)
{
    extern __shared__ float sm[];
    float* sW2 = sm + OFF_W2;
    float* sW3 = sm + OFF_W3;
    float* sW1 = sm + OFF_W1;
    float* sB1 = sm + OFF_B1;
    float* sB2 = sm + OFF_B2;
    float* sB3 = sm + OFF_B3;
    float* sH  = sm + OFF_H;
    float* sLow= sm + OFF_LOW;
    float* sLd = sm + OFF_LD;
    float* U   = sm + OFF_U;    // T1T[128][64] then P[64][144]
    float* T2  = sm + OFF_T2;   // T2T[128][64]

    const int tid = threadIdx.x;
    const long base = (long)blockIdx.x * ROWS;
    const int nrows = min(ROWS, (int)(B - base));

    // ---- stage weights + inputs ----
    #pragma unroll 4
    for (int i = tid; i < 16384; i += NTHREADS) sW2[i] = W2[i];
    #pragma unroll 4
    for (int i = tid; i < 18432; i += NTHREADS) {
        int r = i / OUTP, cc = i - r * OUTP;
        sW3[i] = (cc < OUTD) ? W3[r * OUTD + cc] : 0.0f;
    }
    for (int i = tid; i < 1024; i += NTHREADS) sW1[i] = (i < 7*HID) ? W1[i] : 0.0f;
    if (tid < 128) { sB1[tid] = b1[tid]; sB2[tid] = b2[tid]; }
    if (tid < 144) sB3[tid] = (tid < OUTD) ? b3[tid] : 0.0f;

    for (int i = tid; i < ROWS * XDIM; i += NTHREADS) {
        int r = i / XDIM, cc = i - r * XDIM;
        float v = (r < nrows) ? x[(base + r) * XDIM + cc] : 0.0f;
        if (cc < LOWERD) sLow[r * 4 + cc] = v;
        else             sH[r * 8 + (cc - LOWERD)] = v;
    }
    for (int i = tid; i < ROWS * CDIM; i += NTHREADS) {
        int r = i / CDIM, cc = i - r * CDIM;
        sH[r * 8 + 3 + cc] = (r < nrows) ? c[(base + r) * CDIM + cc] : 0.0f;
    }
    __syncthreads();

    const int tx = tid & 15;          // 16 col-groups
    const int ty = tid >> 4;          // 16 row-groups
    const int r0 = ty * 4;            // 4 rows / thread
    const int c0 = tx * 8;            // 8 cols / thread (GEMM1/2)

    // ---- GEMM1: h1 = relu(h @ W1 + b1), store transposed T1T[col][row] ----
    {
        float acc[4][8];
        #pragma unroll
        for (int j = 0; j < 4; j++)
            #pragma unroll
            for (int i = 0; i < 8; i++) acc[j][i] = sB1[c0 + i];
        #pragma unroll
        for (int k = 0; k < 7; k++) {
            float a[4];
            #pragma unroll
            for (int j = 0; j < 4; j++) a[j] = sH[(r0 + j) * 8 + k];
            float w[8];
            #pragma unroll
            for (int i = 0; i < 8; i++) w[i] = sW1[k * HID + c0 + i];
            #pragma unroll
            for (int j = 0; j < 4; j++)
                #pragma unroll
                for (int i = 0; i < 8; i++) acc[j][i] = fmaf(a[j], w[i], acc[j][i]);
        }
        #pragma unroll
        for (int j = 0; j < 4; j++)
            #pragma unroll
            for (int i = 0; i < 8; i++)
                U[(c0 + i) * ROWS + (r0 + j)] = fmaxf(acc[j][i], 0.0f);
    }
    __syncthreads();

    // ---- GEMM2: h2 = relu(h1 @ W2 + b2), store transposed T2T[col][row] ----
    {
        float acc[4][8];
        #pragma unroll
        for (int j = 0; j < 4; j++)
            #pragma unroll
            for (int i = 0; i < 8; i++) acc[j][i] = sB2[c0 + i];
        #pragma unroll 8
        for (int k = 0; k < HID; k++) {
            float4 a  = *(const float4*)&U[k * ROWS + r0];
            float4 w0 = *(const float4*)&sW2[k * HID + c0];
            float4 w1 = *(const float4*)&sW2[k * HID + c0 + 4];
            float av[4] = {a.x, a.y, a.z, a.w};
            float wv[8] = {w0.x, w0.y, w0.z, w0.w, w1.x, w1.y, w1.z, w1.w};
            #pragma unroll
            for (int j = 0; j < 4; j++)
                #pragma unroll
                for (int i = 0; i < 8; i++) acc[j][i] = fmaf(av[j], wv[i], acc[j][i]);
        }
        #pragma unroll
        for (int j = 0; j < 4; j++)
            #pragma unroll
            for (int i = 0; i < 8; i++)
                T2[(c0 + i) * ROWS + (r0 + j)] = fmaxf(acc[j][i], 0.0f);
    }
    __syncthreads();

    // ---- GEMM3: p = h2 @ W3 + b3, store row-major P[row][144] into U ----
    {
        const int c3 = tx * 9;        // 9 cols / thread -> 144 padded
        float acc[4][9];
        #pragma unroll
        for (int j = 0; j < 4; j++)
            #pragma unroll
            for (int i = 0; i < 9; i++) acc[j][i] = sB3[c3 + i];
        #pragma unroll 8
        for (int k = 0; k < HID; k++) {
            float4 a = *(const float4*)&T2[k * ROWS + r0];
            float av[4] = {a.x, a.y, a.z, a.w};
            float wv[9];
            #pragma unroll
            for (int i = 0; i < 9; i++) wv[i] = sW3[k * OUTP + c3 + i];
            #pragma unroll
            for (int j = 0; j < 4; j++)
                #pragma unroll
                for (int i = 0; i < 9; i++) acc[j][i] = fmaf(av[j], wv[i], acc[j][i]);
        }
        #pragma unroll
        for (int j = 0; j < 4; j++)
            #pragma unroll
            for (int i = 0; i < 9; i++)
                U[(r0 + j) * OUTP + c3 + i] = acc[j][i];
    }
    __syncthreads();

    // ---- Spline epilogue: one thread per (row, dim) ----
    if (tid < ROWS * LOWERD) {
        const int r = tid / 3;
        const int d = tid - r * 3;
        const float* p = &U[r * OUTP + d * SPLD];
        const float xv = sLow[r * 4 + d];
        const bool oob = (xv <= -BOUNDV) || (xv >= BOUNDV);
        const float xm = oob ? -BOUNDV : xv;

        // --- W softmax + bin search ---
        float mW = -1e30f;
        #pragma unroll
        for (int i = 0; i < KNOTS; i++) mW = fmaxf(mW, p[i]);
        float ew[KNOTS];
        float S = 0.0f;
        #pragma unroll
        for (int i = 0; i < KNOTS; i++) { ew[i] = __expf(p[i] - mW); S += ew[i]; }
        const float invS = (2.0f * BOUNDV) / S;

        int idx = 0; float cumex = 0.0f, wsel = ew[0];
        bool found = false; float cum = 0.0f;
        #pragma unroll
        for (int i = 0; i < KNOTS; i++) {
            float cn = cum + ew[i];
            float xk_hi = fmaf(cn, invS, -BOUNDV);
            bool take = (!found) && (xm < xk_hi);
            if (take) { found = true; idx = i; cumex = cum; wsel = ew[i]; }
            cum = cn;
        }
        if (!found) { idx = KNOTS - 1; cumex = cum - ew[KNOTS - 1]; wsel = ew[KNOTS - 1]; }

        const float xk_b = fmaf(cumex, invS, -BOUNDV);
        const float wk   = wsel * invS;

        // --- H softmax (single pass selection) ---
        float mH = -1e30f;
        #pragma unroll
        for (int i = 0; i < KNOTS; i++) mH = fmaxf(mH, p[KNOTS + i]);
        float SH = 0.0f, cumh = 0.0f, hsel = 0.0f;
        #pragma unroll
        for (int i = 0; i < KNOTS; i++) {
            float e = __expf(p[KNOTS + i] - mH);
            SH += e;
            if (i < idx)  cumh += e;
            if (i == idx) hsel = e;
        }
        const float invSH = (2.0f * BOUNDV) / SH;
        const float yk_b = fmaf(cumh, invSH, -BOUNDV);
        const float hk   = hsel * invSH;

        // --- derivatives (only 2 needed) ---
        float d0 = 1.0f, d1 = 1.0f;
        if (idx > 0)          d0 = softplus_f(p[2 * KNOTS + idx - 1]);
        if (idx < KNOTS - 1)  d1 = softplus_f(p[2 * KNOTS + idx]);

        // --- RQS forward ---
        const float sk = hk / wk;
        float relx = (xm - xk_b) / wk;
        relx = fminf(fmaxf(relx, 0.0f), 1.0f);
        const float omr = 1.0f - relx;
        const float r1 = relx * omr;
        const float den = sk + (d1 + d0 - 2.0f * sk) * r1;
        const float num = hk * (sk * relx * relx + d0 * r1);
        float y = yk_b + num / den;
        const float arg = d1 * relx * relx + 2.0f * sk * r1 + d0 * omr * omr;
        float ld = __logf((sk * sk * arg) / (den * den));
        if (oob) { y = xv; ld = 0.0f; }

        sLd[r * 4 + d] = ld;
        if (r < nrows) {
            out[(base + r) * XDIM + d] = y;
            out[(base + r) * XDIM + LOWERD + d] = sH[r * 8 + d];  // upper passthrough
        }
    }
    __syncthreads();

    if (tid < ROWS && tid < nrows) {
        out[(long)B * XDIM + base + tid] =
            sLd[tid * 4] + sLd[tid * 4 + 1] + sLd[tid * 4 + 2];
    }
}

extern "C" void kernel_launch(void* const* d_in, const int* in_sizes, int n_in,
                              void* d_out, int out_size)
{
    const float* x  = (const float*)d_in[0];
    const float* c  = (const float*)d_in[1];
    const float* W1 = (const float*)d_in[2];
    const float* b1 = (const float*)d_in[3];
    const float* W2 = (const float*)d_in[4];
    const float* b2 = (const float*)d_in[5];
    const float* W3 = (const float*)d_in[6];
    const float* b3 = (const float*)d_in[7];
    (void)n_in; (void)out_size;

    const int B = in_sizes[0] / XDIM;
    float* out = (float*)d_out;

    cudaFuncSetAttribute(nsc_kernel, cudaFuncAttributeMaxDynamicSharedMemorySize,
                         SMEM_BYTES);

    dim3 grid((B + ROWS - 1) / ROWS);
    nsc_kernel<<<grid, NTHREADS, SMEM_BYTES>>>(x, c, W1, b1, W2, b2, W3, b3, out, B);
}

// round 3
// speedup vs baseline: 4.7585x; 4.7585x over previous
#include <cuda_runtime.h>
#include <cuda_fp16.h>
#include <math.h>
#include <stdint.h>

#define KNOTS   16
#define BOUNDV  5.0f
#define XDIM    6
#define CDIM    4
#define HID     128
#define SPLD    47
#define LOWERD  3
#define OUTD    141
#define NPAD    144
#define MROWS   128
#define NTHREADS 256

#define AST   136   // A tile stride (halves)
#define W2ST  136
#define W3ST  152
#define PST   147   // P stride (floats)

// ---- smem byte offsets ----
#define OFF_AH   0                     // 34816  Ah fp16 [128][136]
#define OFF_AL   34816                 // 34816  Al fp16 [128][136]
#define OFF_W2   69632                 // 34816  W2 fp16 [k=128][n pad 136]
#define OFF_W3   104448                // 38912  W3 fp16 [k=128][n pad 152]
#define OFF_P    143360                // 75264  P fp32 [128][147]
#define OFF_IN   218624                // 4096
#define OFF_LOW  222720                // 2048
#define OFF_W1   224768                // 3584
#define OFF_B1   228352                // 512
#define OFF_B2   228864                // 512
#define OFF_B3   229376                // 576
#define OFF_LD   229952                // 2048
#define SMEM_BYTES 232000

static __device__ __forceinline__ uint32_t smem_u32(const void* p) {
    uint32_t a;
    asm("{ .reg .u64 t; cvta.to.shared.u64 t, %1; cvt.u32.u64 %0, t; }" : "=r"(a) : "l"(p));
    return a;
}

static __device__ __forceinline__ void ldsm_x4(uint32_t a, uint32_t& r0, uint32_t& r1,
                                               uint32_t& r2, uint32_t& r3) {
    asm volatile("ldmatrix.sync.aligned.m8n8.x4.shared.b16 {%0,%1,%2,%3}, [%4];"
                 : "=r"(r0), "=r"(r1), "=r"(r2), "=r"(r3) : "r"(a));
}
static __device__ __forceinline__ void ldsm_x4t(uint32_t a, uint32_t& r0, uint32_t& r1,
                                                uint32_t& r2, uint32_t& r3) {
    asm volatile("ldmatrix.sync.aligned.m8n8.x4.trans.shared.b16 {%0,%1,%2,%3}, [%4];"
                 : "=r"(r0), "=r"(r1), "=r"(r2), "=r"(r3) : "r"(a));
}
static __device__ __forceinline__ void ldsm_x2t(uint32_t a, uint32_t& r0, uint32_t& r1) {
    asm volatile("ldmatrix.sync.aligned.m8n8.x2.trans.shared.b16 {%0,%1}, [%2];"
                 : "=r"(r0), "=r"(r1) : "r"(a));
}
static __device__ __forceinline__ void mma16816(float* c, const uint32_t* a,
                                                uint32_t b0, uint32_t b1) {
    asm volatile("mma.sync.aligned.m16n8k16.row.col.f32.f16.f16.f32 "
                 "{%0,%1,%2,%3}, {%4,%5,%6,%7}, {%8,%9}, {%0,%1,%2,%3};"
                 : "+f"(c[0]), "+f"(c[1]), "+f"(c[2]), "+f"(c[3])
                 : "r"(a[0]), "r"(a[1]), "r"(a[2]), "r"(a[3]), "r"(b0), "r"(b1));
}

__device__ __forceinline__ float softplus_f(float v) {
    return fmaxf(v, 0.0f) + log1pf(__expf(-fabsf(v)));
}

__global__ __launch_bounds__(NTHREADS, 1)
void nsc_hmma_kernel(const float* __restrict__ x, const float* __restrict__ c,
                     const float* __restrict__ W1, const float* __restrict__ b1,
                     const float* __restrict__ W2, const float* __restrict__ b2,
                     const float* __restrict__ W3, const float* __restrict__ b3,
                     float* __restrict__ out, int B, int ntiles)
{
    extern __shared__ char smb[];
    const uint32_t sb = smem_u32(smb);

    __half* hAh = (__half*)(smb + OFF_AH);
    __half* hAl = (__half*)(smb + OFF_AL);
    __half* hW2 = (__half*)(smb + OFF_W2);
    __half* hW3 = (__half*)(smb + OFF_W3);
    float* sP   = (float*)(smb + OFF_P);
    float* sIn  = (float*)(smb + OFF_IN);
    float* sLow = (float*)(smb + OFF_LOW);
    float* sW1  = (float*)(smb + OFF_W1);
    float* sB1  = (float*)(smb + OFF_B1);
    float* sB2  = (float*)(smb + OFF_B2);
    float* sB3  = (float*)(smb + OFF_B3);
    float* sLd  = (float*)(smb + OFF_LD);

    const int tid = threadIdx.x;
    const int warp = tid >> 5;
    const int lane = tid & 31;
    const int wm = warp >> 1;          // 0..3 -> m0 = wm*32
    const int wn = warp & 1;           // 0..1
    const int m0 = wm * 32;
    const int lr = lane & 15;
    const int lc = (lane >> 4) * 8;
    const int grow = lane >> 2;        // D-fragment row-in-8
    const int gcol = (lane & 3) * 2;   // D-fragment col pair

    // ---- one-time weight staging (per CTA) ----
    for (int i = tid; i < HID * HID; i += NTHREADS) {
        int k = i >> 7, n = i & 127;
        hW2[k * W2ST + n] = __float2half_rn(W2[i]);
    }
    for (int i = tid; i < HID * NPAD; i += NTHREADS) {
        int k = i / NPAD, n = i - k * NPAD;
        hW3[k * W3ST + n] = __float2half_rn((n < OUTD) ? W3[k * OUTD + n] : 0.0f);
    }
    for (int i = tid; i < 7 * HID; i += NTHREADS) sW1[i] = W1[i];
    if (tid < HID) { sB1[tid] = b1[tid]; sB2[tid] = b2[tid]; }
    if (tid < NPAD) sB3[tid] = (tid < OUTD) ? b3[tid] : 0.0f;

    for (long tile = blockIdx.x; tile < ntiles; tile += gridDim.x) {
        const long base = tile * MROWS;
        const int nrows = (int)min((long)MROWS, (long)B - base);
        __syncthreads();   // previous tile fully done

        // ---- stage inputs ----
        for (int i = tid; i < MROWS * XDIM; i += NTHREADS) {
            int r = i / XDIM, cc = i - r * XDIM;
            float v = (r < nrows) ? x[(base + r) * XDIM + cc] : 0.0f;
            if (cc < LOWERD) sLow[r * 4 + cc] = v;
            else             sIn[r * 8 + (cc - LOWERD)] = v;
        }
        for (int i = tid; i < MROWS * CDIM; i += NTHREADS) {
            int r = i >> 2, cc = i & 3;
            sIn[r * 8 + 3 + cc] = (r < nrows) ? c[(base + r) * CDIM + cc] : 0.0f;
        }
        __syncthreads();

        // ---- layer 1 (fp32) -> split fp16 A ----
        for (int t = tid; t < MROWS * 64; t += NTHREADS) {
            int r = t >> 6, np = (t & 63) << 1;
            float a0 = sB1[np], a1 = sB1[np + 1];
            const float* inr = &sIn[r * 8];
            #pragma unroll
            for (int k = 0; k < 7; k++) {
                float iv = inr[k];
                a0 = fmaf(iv, sW1[k * HID + np], a0);
                a1 = fmaf(iv, sW1[k * HID + np + 1], a1);
            }
            a0 = fmaxf(a0, 0.0f); a1 = fmaxf(a1, 0.0f);
            __half h0 = __float2half_rn(a0), h1v = __float2half_rn(a1);
            __half l0 = __float2half_rn(a0 - __half2float(h0));
            __half l1 = __float2half_rn(a1 - __half2float(h1v));
            *(__half2*)&hAh[r * AST + np] = __halves2half2(h0, h1v);
            *(__half2*)&hAl[r * AST + np] = __halves2half2(l0, l1);
        }
        __syncthreads();

        // ---- GEMM2: 128x128x128, split-A ----
        float acc[2][8][4];
        {
            #pragma unroll
            for (int mt = 0; mt < 2; mt++)
                #pragma unroll
                for (int nt = 0; nt < 8; nt++)
                    #pragma unroll
                    for (int q = 0; q < 4; q++) acc[mt][nt][q] = 0.0f;
            const int n0 = wn * 64;
            #pragma unroll
            for (int kk = 0; kk < 8; kk++) {
                const int kb = kk * 16;
                uint32_t ah[2][4], al[2][4], bb[4][4];
                #pragma unroll
                for (int mt = 0; mt < 2; mt++) {
                    uint32_t aoff = (uint32_t)(((m0 + mt * 16 + lr) * AST + kb + lc) * 2);
                    ldsm_x4(sb + OFF_AH + aoff, ah[mt][0], ah[mt][1], ah[mt][2], ah[mt][3]);
                    ldsm_x4(sb + OFF_AL + aoff, al[mt][0], al[mt][1], al[mt][2], al[mt][3]);
                }
                #pragma unroll
                for (int np = 0; np < 4; np++) {
                    uint32_t boff = (uint32_t)(((kb + lr) * W2ST + n0 + np * 16 + lc) * 2);
                    ldsm_x4t(sb + OFF_W2 + boff, bb[np][0], bb[np][1], bb[np][2], bb[np][3]);
                }
                #pragma unroll
                for (int mt = 0; mt < 2; mt++)
                    #pragma unroll
                    for (int np = 0; np < 4; np++)
                        #pragma unroll
                        for (int j = 0; j < 2; j++) {
                            float* cc4 = acc[mt][np * 2 + j];
                            mma16816(cc4, ah[mt], bb[np][2 * j], bb[np][2 * j + 1]);
                            mma16816(cc4, al[mt], bb[np][2 * j], bb[np][2 * j + 1]);
                        }
            }
        }
        __syncthreads();  // all warps done reading h1 tiles

        // ---- h2 = relu(D + b2) -> split fp16 A (overwrite) ----
        {
            const int n0 = wn * 64;
            #pragma unroll
            for (int mt = 0; mt < 2; mt++)
                #pragma unroll
                for (int nt = 0; nt < 8; nt++) {
                    int col = n0 + nt * 8 + gcol;
                    float bb0 = sB2[col], bb1 = sB2[col + 1];
                    #pragma unroll
                    for (int h = 0; h < 2; h++) {
                        int r = m0 + mt * 16 + grow + h * 8;
                        float v0 = fmaxf(acc[mt][nt][2 * h]     + bb0, 0.0f);
                        float v1 = fmaxf(acc[mt][nt][2 * h + 1] + bb1, 0.0f);
                        __half h0 = __float2half_rn(v0), h1v = __float2half_rn(v1);
                        __half l0 = __float2half_rn(v0 - __half2float(h0));
                        __half l1 = __float2half_rn(v1 - __half2float(h1v));
                        *(__half2*)&hAh[r * AST + col] = __halves2half2(h0, h1v);
                        *(__half2*)&hAl[r * AST + col] = __halves2half2(l0, l1);
                    }
                }
        }
        __syncthreads();

        // ---- GEMM3: 128x144x128, split-A, 9 n-tiles/warp ----
        {
            float a3[2][9][4];
            #pragma unroll
            for (int mt = 0; mt < 2; mt++)
                #pragma unroll
                for (int nt = 0; nt < 9; nt++)
                    #pragma unroll
                    for (int q = 0; q < 4; q++) a3[mt][nt][q] = 0.0f;
            const int n0 = wn * 72;
            #pragma unroll
            for (int kk = 0; kk < 8; kk++) {
                const int kb = kk * 16;
                uint32_t ah[2][4], al[2][4], bb[4][4], be[2];
                #pragma unroll
                for (int mt = 0; mt < 2; mt++) {
                    uint32_t aoff = (uint32_t)(((m0 + mt * 16 + lr) * AST + kb + lc) * 2);
                    ldsm_x4(sb + OFF_AH + aoff, ah[mt][0], ah[mt][1], ah[mt][2], ah[mt][3]);
                    ldsm_x4(sb + OFF_AL + aoff, al[mt][0], al[mt][1], al[mt][2], al[mt][3]);
                }
                #pragma unroll
                for (int np = 0; np < 4; np++) {
                    uint32_t boff = (uint32_t)(((kb + lr) * W3ST + n0 + np * 16 + lc) * 2);
                    ldsm_x4t(sb + OFF_W3 + boff, bb[np][0], bb[np][1], bb[np][2], bb[np][3]);
                }
                {
                    uint32_t boff = (uint32_t)(((kb + lr) * W3ST + n0 + 64) * 2);
                    ldsm_x2t(sb + OFF_W3 + boff, be[0], be[1]);
                }
                #pragma unroll
                for (int mt = 0; mt < 2; mt++) {
                    #pragma unroll
                    for (int np = 0; np < 4; np++)
                        #pragma unroll
                        for (int j = 0; j < 2; j++) {
                            float* cc4 = a3[mt][np * 2 + j];
                            mma16816(cc4, ah[mt], bb[np][2 * j], bb[np][2 * j + 1]);
                            mma16816(cc4, al[mt], bb[np][2 * j], bb[np][2 * j + 1]);
                        }
                    mma16816(a3[mt][8], ah[mt], be[0], be[1]);
                    mma16816(a3[mt][8], al[mt], be[0], be[1]);
                }
            }
            // P = D + b3
            #pragma unroll
            for (int mt = 0; mt < 2; mt++)
                #pragma unroll
                for (int nt = 0; nt < 9; nt++) {
                    int col = n0 + nt * 8 + gcol;
                    float bb0 = sB3[col], bb1 = sB3[col + 1];
                    #pragma unroll
                    for (int h = 0; h < 2; h++) {
                        int r = m0 + mt * 16 + grow + h * 8;
                        sP[r * PST + col]     = a3[mt][nt][2 * h]     + bb0;
                        sP[r * PST + col + 1] = a3[mt][nt][2 * h + 1] + bb1;
                    }
                }
        }
        __syncthreads();

        // ---- spline epilogue ----
        for (int item = tid; item < MROWS * LOWERD; item += NTHREADS) {
            const int r = item / 3;
            const int d = item - r * 3;
            const float* p = &sP[r * PST + d * SPLD];
            const float xv = sLow[r * 4 + d];
            const bool oob = (xv <= -BOUNDV) || (xv >= BOUNDV);
            const float xm = oob ? -BOUNDV : xv;

            float mW = -1e30f;
            #pragma unroll
            for (int i = 0; i < KNOTS; i++) mW = fmaxf(mW, p[i]);
            float ew[KNOTS], S = 0.0f;
            #pragma unroll
            for (int i = 0; i < KNOTS; i++) { ew[i] = __expf(p[i] - mW); S += ew[i]; }
            const float invS = (2.0f * BOUNDV) / S;

            int idx = 0; float cumex = 0.0f, wsel = ew[0];
            bool found = false; float cum = 0.0f;
            #pragma unroll
            for (int i = 0; i < KNOTS; i++) {
                float cn = cum + ew[i];
                bool take = (!found) && (xm < fmaf(cn, invS, -BOUNDV));
                if (take) { found = true; idx = i; cumex = cum; wsel = ew[i]; }
                cum = cn;
            }
            if (!found) { idx = KNOTS - 1; cumex = cum - ew[KNOTS - 1]; wsel = ew[KNOTS - 1]; }

            const float xk_b = fmaf(cumex, invS, -BOUNDV);
            const float wk   = wsel * invS;

            float mH = -1e30f;
            #pragma unroll
            for (int i = 0; i < KNOTS; i++) mH = fmaxf(mH, p[KNOTS + i]);
            float SH = 0.0f, cumh = 0.0f, hsel = 0.0f;
            #pragma unroll
            for (int i = 0; i < KNOTS; i++) {
                float e = __expf(p[KNOTS + i] - mH);
                SH += e;
                if (i < idx)  cumh += e;
                if (i == idx) hsel = e;
            }
            const float invSH = (2.0f * BOUNDV) / SH;
            const float yk_b = fmaf(cumh, invSH, -BOUNDV);
            const float hk   = hsel * invSH;

            float d0 = 1.0f, d1 = 1.0f;
            if (idx > 0)         d0 = softplus_f(p[2 * KNOTS + idx - 1]);
            if (idx < KNOTS - 1) d1 = softplus_f(p[2 * KNOTS + idx]);

            const float sk = hk / wk;
            float relx = fminf(fmaxf((xm - xk_b) / wk, 0.0f), 1.0f);
            const float omr = 1.0f - relx;
            const float r1 = relx * omr;
            const float den = sk + (d1 + d0 - 2.0f * sk) * r1;
            const float num = hk * (sk * relx * relx + d0 * r1);
            float y = yk_b + num / den;
            const float arg = d1 * relx * relx + 2.0f * sk * r1 + d0 * omr * omr;
            float ld = __logf((sk * sk * arg) / (den * den));
            if (oob) { y = xv; ld = 0.0f; }

            sLd[r * 4 + d] = ld;
            if (r < nrows) {
                out[(base + r) * XDIM + d] = y;
                out[(base + r) * XDIM + LOWERD + d] = sIn[r * 8 + d];
            }
        }
        __syncthreads();
        if (tid < MROWS && tid < nrows)
            out[(long)B * XDIM + base + tid] =
                sLd[tid * 4] + sLd[tid * 4 + 1] + sLd[tid * 4 + 2];
    }
}

extern "C" void kernel_launch(void* const* d_in, const int* in_sizes, int n_in,
                              void* d_out, int out_size)
{
    const float* x  = (const float*)d_in[0];
    const float* c  = (const float*)d_in[1];
    const float* W1 = (const float*)d_in[2];
    const float* b1 = (const float*)d_in[3];
    const float* W2 = (const float*)d_in[4];
    const float* b2 = (const float*)d_in[5];
    const float* W3 = (const float*)d_in[6];
    const float* b3 = (const float*)d_in[7];
    (void)n_in; (void)out_size;

    const int B = in_sizes[0] / XDIM;
    const int ntiles = (B + MROWS - 1) / MROWS;
    float* out = (float*)d_out;

    int sms = 148;
    cudaDeviceGetAttribute(&sms, cudaDevAttrMultiProcessorCount, 0);
    int grid = sms < ntiles ? sms : ntiles;

    cudaFuncSetAttribute(nsc_hmma_kernel, cudaFuncAttributeMaxDynamicSharedMemorySize,
                         SMEM_BYTES);
    nsc_hmma_kernel<<<grid, NTHREADS, SMEM_BYTES>>>(x, c, W1, b1, W2, b2, W3, b3,
                                                    out, B, ntiles);
}